// round 12
// baseline (speedup 1.0000x reference)
#include <cuda_runtime.h>
#include <math.h>
#include <stdint.h>

#define HEADS 8
#define BATCH 8
#define NSEQ 1024
#define DIM 512
#define DH 64
#define HB 64            /* HEADS*BATCH */
#define ROWS 8192        /* BATCH*NSEQ  */
#define RT 65536         /* HB*NSEQ     */
#define FEPS 1e-6f
#define FGAMMA 0.01f
#define COVSCALE ((0.001f/1024.f)/(8.0f+1e-6f))

/* ------------------------- scratch (device globals) ------------------------ */
__device__ float g_xn[(size_t)ROWS*DIM];
__device__ float g_fq[(size_t)RT*DH];
__device__ float g_fk[(size_t)RT*DH];
__device__ float g_fv[(size_t)RT*DH];
__device__ float g_dots[(size_t)RT*NSEQ];
__device__ float g_nq[RT], g_muq[RT], g_nk[RT], g_sk[RT], g_qdkm[RT];
__device__ float g_kmean[HB*DH];
__device__ float g_skm[HB];
__device__ float g_qg[HEADS*DH], g_kg[HEADS*DH];
__device__ double g_mom[HEADS][9];
__device__ float g_coef[HEADS*2];
__device__ float g_oh[(size_t)ROWS*DIM];

/* ---------------------- packed f32x2 FMA helpers --------------------------- */
__device__ __forceinline__ unsigned long long splat2(float x) {
    unsigned long long r;
    asm("mov.b64 %0, {%1, %1};" : "=l"(r) : "f"(x));
    return r;
}
__device__ __forceinline__ void fma2(unsigned long long& d,
                                     unsigned long long a, unsigned long long b) {
    asm("fma.rn.f32x2 %0, %1, %2, %0;" : "+l"(d) : "l"(a), "l"(b));
}
__device__ __forceinline__ float2 unpack2(unsigned long long v) {
    float2 f;
    asm("mov.b64 {%0, %1}, %2;" : "=f"(f.x), "=f"(f.y) : "l"(v));
    return f;
}
/* one k-step of a 4x4 microtile: a4 = 4 A-values, b0/b1 = packed B pairs */
#define FMA2_STEP(a4, b0, b1)                                                  \
    do {                                                                       \
        unsigned long long s0 = splat2((a4).x), s1 = splat2((a4).y);           \
        unsigned long long s2 = splat2((a4).z), s3 = splat2((a4).w);           \
        fma2(acc00, s0, b0); fma2(acc01, s0, b1);                              \
        fma2(acc10, s1, b0); fma2(acc11, s1, b1);                              \
        fma2(acc20, s2, b0); fma2(acc21, s2, b1);                              \
        fma2(acc30, s3, b0); fma2(acc31, s3, b1);                              \
    } while (0)

/* ------------------------------ zero moments ------------------------------ */
__global__ void zero_mom_kernel() {
    int t = threadIdx.x;
    if (t < HEADS*9) ((double*)g_mom)[t] = 0.0;
}

/* ------------------------------- layernorm -------------------------------- */
__global__ void ln_kernel(const float* __restrict__ x,
                          const float* __restrict__ g,
                          const float* __restrict__ bb) {
    int row = blockIdx.x;
    int t = threadIdx.x;                 /* 128 threads */
    const float* xr = x + (size_t)row * DIM;
    float v[4]; float s = 0.f, s2 = 0.f;
#pragma unroll
    for (int i = 0; i < 4; i++) {
        float val = xr[t + 128*i];
        v[i] = val; s += val; s2 += val*val;
    }
    __shared__ float sh[8];
    for (int o = 16; o > 0; o >>= 1) {
        s  += __shfl_down_sync(0xffffffffu, s,  o);
        s2 += __shfl_down_sync(0xffffffffu, s2, o);
    }
    int w = t >> 5, lane = t & 31;
    if (lane == 0) { sh[w] = s; sh[4+w] = s2; }
    __syncthreads();
    if (t == 0) {
        float ts = 0.f, ts2 = 0.f;
        for (int i = 0; i < 4; i++) { ts += sh[i]; ts2 += sh[4+i]; }
        sh[0] = ts; sh[4] = ts2;
    }
    __syncthreads();
    float mu  = sh[0] * (1.f/DIM);
    float var = sh[4] * (1.f/DIM) - mu*mu;
    float inv = rsqrtf(var + 1e-5f);
    float* orow = g_xn + (size_t)row * DIM;
#pragma unroll
    for (int i = 0; i < 4; i++) {
        int c = t + 128*i;
        orow[c] = (v[i] - mu) * inv * g[c] + bb[c];
    }
}

/* -------------------- projection GEMM: g_xn @ W -> f[h,b,n,d] -------------- */
__global__ void gemm_proj_kernel(const float* __restrict__ Bw, int which) {
    __shared__ __align__(16) float As[16][68];
    __shared__ __align__(16) float Bs[16][64];
    int tid = threadIdx.x;               /* 256 */
    int tx = tid & 15, ty = tid >> 4;
    int bm = blockIdx.y * 64;
    int bn = blockIdx.x * 64;
    unsigned long long acc00 = 0ull, acc01 = 0ull, acc10 = 0ull, acc11 = 0ull;
    unsigned long long acc20 = 0ull, acc21 = 0ull, acc30 = 0ull, acc31 = 0ull;
    int am = tid >> 2;
    int ak = (tid & 3) * 4;
    int bk = tid >> 4;
    int bn4 = (tid & 15) * 4;
    const float* A = g_xn;
    for (int k0 = 0; k0 < DIM; k0 += 16) {
        float4 ga = *(const float4*)(A + (size_t)(bm+am)*DIM + k0 + ak);
        float4 gb = *(const float4*)(Bw + (size_t)(k0+bk)*DIM + bn + bn4);
        As[ak+0][am] = ga.x; As[ak+1][am] = ga.y;
        As[ak+2][am] = ga.z; As[ak+3][am] = ga.w;
        *(float4*)&Bs[bk][bn4] = gb;
        __syncthreads();
#pragma unroll
        for (int k = 0; k < 16; ++k) {
            float4 a4 = *(const float4*)&As[k][ty*4];
            unsigned long long b0 = *(const unsigned long long*)&Bs[k][tx*4];
            unsigned long long b1 = *(const unsigned long long*)&Bs[k][tx*4+2];
            FMA2_STEP(a4, b0, b1);
        }
        __syncthreads();
    }
    float* C = (which == 0) ? g_fq : ((which == 1) ? g_fk : g_fv);
    int h_ = bn >> 6;                    /* tile is within one head */
    float2 r0a = unpack2(acc00), r0b = unpack2(acc01);
    float2 r1a = unpack2(acc10), r1b = unpack2(acc11);
    float2 r2a = unpack2(acc20), r2b = unpack2(acc21);
    float2 r3a = unpack2(acc30), r3b = unpack2(acc31);
    float4 ov[4];
    ov[0] = make_float4(r0a.x, r0a.y, r0b.x, r0b.y);
    ov[1] = make_float4(r1a.x, r1a.y, r1b.x, r1b.y);
    ov[2] = make_float4(r2a.x, r2a.y, r2b.x, r2b.y);
    ov[3] = make_float4(r3a.x, r3a.y, r3b.x, r3b.y);
#pragma unroll
    for (int i = 0; i < 4; i++) {
        int r = bm + ty*4 + i;
        int b_ = r >> 10, n = r & 1023;
        *(float4*)(C + (((size_t)(h_*BATCH + b_)) << 16) + (n << 6) + tx*4) = ov[i];
    }
}

/* ------------------------ output GEMM: g_oh @ W + b ------------------------ */
__global__ void gemm_out_kernel(const float* __restrict__ Bw,
                                const float* __restrict__ bias,
                                float* __restrict__ Cout) {
    __shared__ __align__(16) float As[16][68];
    __shared__ __align__(16) float Bs[16][64];
    int tid = threadIdx.x;
    int tx = tid & 15, ty = tid >> 4;
    int bm = blockIdx.y * 64;
    int bn = blockIdx.x * 64;
    unsigned long long acc00 = 0ull, acc01 = 0ull, acc10 = 0ull, acc11 = 0ull;
    unsigned long long acc20 = 0ull, acc21 = 0ull, acc30 = 0ull, acc31 = 0ull;
    int am = tid >> 2;
    int ak = (tid & 3) * 4;
    int bk = tid >> 4;
    int bn4 = (tid & 15) * 4;
    const float* A = g_oh;
    for (int k0 = 0; k0 < DIM; k0 += 16) {
        float4 ga = *(const float4*)(A + (size_t)(bm+am)*DIM + k0 + ak);
        float4 gb = *(const float4*)(Bw + (size_t)(k0+bk)*DIM + bn + bn4);
        As[ak+0][am] = ga.x; As[ak+1][am] = ga.y;
        As[ak+2][am] = ga.z; As[ak+3][am] = ga.w;
        *(float4*)&Bs[bk][bn4] = gb;
        __syncthreads();
#pragma unroll
        for (int k = 0; k < 16; ++k) {
            float4 a4 = *(const float4*)&As[k][ty*4];
            unsigned long long b0 = *(const unsigned long long*)&Bs[k][tx*4];
            unsigned long long b1 = *(const unsigned long long*)&Bs[k][tx*4+2];
            FMA2_STEP(a4, b0, b1);
        }
        __syncthreads();
    }
    float4 bv4 = *(const float4*)(bias + bn + tx*4);
    float2 r0a = unpack2(acc00), r0b = unpack2(acc01);
    float2 r1a = unpack2(acc10), r1b = unpack2(acc11);
    float2 r2a = unpack2(acc20), r2b = unpack2(acc21);
    float2 r3a = unpack2(acc30), r3b = unpack2(acc31);
    float4 ov[4];
    ov[0] = make_float4(r0a.x+bv4.x, r0a.y+bv4.y, r0b.x+bv4.z, r0b.y+bv4.w);
    ov[1] = make_float4(r1a.x+bv4.x, r1a.y+bv4.y, r1b.x+bv4.z, r1b.y+bv4.w);
    ov[2] = make_float4(r2a.x+bv4.x, r2a.y+bv4.y, r2b.x+bv4.z, r2b.y+bv4.w);
    ov[3] = make_float4(r3a.x+bv4.x, r3a.y+bv4.y, r3b.x+bv4.z, r3b.y+bv4.w);
#pragma unroll
    for (int i = 0; i < 4; i++) {
        int r = bm + ty*4 + i;
        *(float4*)(Cout + (size_t)r*DIM + bn + tx*4) = ov[i];
    }
}

/* ----------------- per-row stats: norms / means / sums --------------------- */
__global__ void rowstats_kernel() {
    int blk = blockIdx.x;                /* 16384 */
    int tensor = blk >> 13;
    int rowbase = (blk & 8191) * 8;
    int w = threadIdx.x >> 5, lane = threadIdx.x & 31;
    int row = rowbase + w;
    const float* f = (tensor == 0) ? g_fq : g_fk;
    float a = f[(size_t)row*DH + lane];
    float b = f[(size_t)row*DH + 32 + lane];
    float s = a + b, s2 = a*a + b*b;
    for (int o = 16; o > 0; o >>= 1) {
        s  += __shfl_down_sync(0xffffffffu, s,  o);
        s2 += __shfl_down_sync(0xffffffffu, s2, o);
    }
    if (lane == 0) {
        if (tensor == 0) { g_nq[row] = sqrtf(s2); g_muq[row] = s * (1.f/DH); }
        else             { g_nk[row] = sqrtf(s2); g_sk[row] = s; }
    }
}

/* ------------------------- kmean over n, skm over d ------------------------ */
__global__ void kmean_kernel() {
    int hb = blockIdx.x;
    int grp = threadIdx.x >> 6;
    int dd = threadIdx.x & 63;
    float acc = 0.f;
    const float* base = g_fk + (size_t)hb * NSEQ * DH;
    for (int n = grp; n < NSEQ; n += 8) acc += base[(size_t)n*DH + dd];
    __shared__ float sh[8][64];
    sh[grp][dd] = acc;
    __syncthreads();
    if (grp == 0) {
        float t = 0.f;
#pragma unroll
        for (int g = 0; g < 8; g++) t += sh[g][dd];
        t *= (1.f/NSEQ);
        g_kmean[hb*DH + dd] = t;
        sh[0][dd] = t;
    }
    __syncthreads();
    if (threadIdx.x == 0) {
        float t = 0.f;
        for (int i = 0; i < DH; i++) t += sh[0][i];
        g_skm[hb] = t;
    }
}

/* --------------------------- q . kmean per row ----------------------------- */
__global__ void qdkm_kernel() {
    int row = blockIdx.x*8 + (threadIdx.x >> 5);
    int lane = threadIdx.x & 31;
    int hb = row >> 10;
    float a = g_fq[(size_t)row*DH + lane]      * g_kmean[hb*DH + lane]
            + g_fq[(size_t)row*DH + 32 + lane] * g_kmean[hb*DH + 32 + lane];
    for (int o = 16; o > 0; o >>= 1) a += __shfl_down_sync(0xffffffffu, a, o);
    if (lane == 0) g_qdkm[row] = a;
}

/* --------------------- q_g / k_g: mean over (b,n) per head ----------------- */
__global__ void qgkg_kernel() {
    int t = blockIdx.x >> 3;
    int h = blockIdx.x & 7;
    const float* f = (t == 0) ? g_fq : g_fk;
    int grp = threadIdx.x >> 6, dd = threadIdx.x & 63;
    float acc = 0.f;
    const float* base = f + (size_t)h * BATCH * NSEQ * DH;
    for (int idx = grp; idx < BATCH*NSEQ; idx += 8) acc += base[(size_t)idx*DH + dd];
    __shared__ float sh[8][64];
    sh[grp][dd] = acc;
    __syncthreads();
    if (grp == 0) {
        float tt = 0.f;
#pragma unroll
        for (int g = 0; g < 8; g++) tt += sh[g][dd];
        float* outp = (t == 0) ? g_qg : g_kg;
        outp[h*DH + dd] = tt * (1.f/(BATCH*NSEQ));
    }
}

/* -------------------- batched QK^T GEMM (dots, K=64 one-shot) -------------- */
__global__ void dots_kernel() {
    int hb = blockIdx.z;
    int bm = blockIdx.y * 64, bn = blockIdx.x * 64;
    __shared__ __align__(16) float As[64][68];
    __shared__ __align__(16) float Bs[64][68];
    int tid = threadIdx.x, tx = tid & 15, ty = tid >> 4;
    const float* qa = g_fq + (size_t)hb * NSEQ * DH;
    const float* kb = g_fk + (size_t)hb * NSEQ * DH;
#pragma unroll
    for (int j = 0; j < 4; j++) {
        int idx = tid + 256*j;
        int m = idx >> 4; int kq = (idx & 15) * 4;
        float4 va = *(const float4*)(qa + (size_t)(bm+m)*DH + kq);
        As[kq+0][m] = va.x; As[kq+1][m] = va.y; As[kq+2][m] = va.z; As[kq+3][m] = va.w;
        float4 vb = *(const float4*)(kb + (size_t)(bn+m)*DH + kq);
        Bs[kq+0][m] = vb.x; Bs[kq+1][m] = vb.y; Bs[kq+2][m] = vb.z; Bs[kq+3][m] = vb.w;
    }
    __syncthreads();
    unsigned long long acc00 = 0ull, acc01 = 0ull, acc10 = 0ull, acc11 = 0ull;
    unsigned long long acc20 = 0ull, acc21 = 0ull, acc30 = 0ull, acc31 = 0ull;
#pragma unroll 16
    for (int k = 0; k < 64; k++) {
        float4 a4 = *(const float4*)&As[k][ty*4];
        unsigned long long b0 = *(const unsigned long long*)&Bs[k][tx*4];
        unsigned long long b1 = *(const unsigned long long*)&Bs[k][tx*4+2];
        FMA2_STEP(a4, b0, b1);
    }
    float* drow = g_dots + ((size_t)hb << 20);
    float2 r0a = unpack2(acc00), r0b = unpack2(acc01);
    float2 r1a = unpack2(acc10), r1b = unpack2(acc11);
    float2 r2a = unpack2(acc20), r2b = unpack2(acc21);
    float2 r3a = unpack2(acc30), r3b = unpack2(acc31);
    float4 ov[4];
    ov[0] = make_float4(r0a.x, r0a.y, r0b.x, r0b.y);
    ov[1] = make_float4(r1a.x, r1a.y, r1b.x, r1b.y);
    ov[2] = make_float4(r2a.x, r2a.y, r2b.x, r2b.y);
    ov[3] = make_float4(r3a.x, r3a.y, r3b.x, r3b.y);
#pragma unroll
    for (int i = 0; i < 4; i++)
        *(float4*)(drow + (size_t)(bm + ty*4 + i)*NSEQ + bn + tx*4) = ov[i];
}

/* ----------------------- global moment accumulation ------------------------ */
__global__ void moments_kernel() {
    int blk = blockIdx.x;                /* 1024 blocks, 64 rows each */
    int row0 = blk * 64;
    int h = row0 >> 13;
    int hb = row0 >> 10;
    int t = threadIdx.x;                 /* 128 */
    int mb = t * 8;
    float rnk[8], rnkm[8], skv[8];
    const float skm = g_skm[hb];
#pragma unroll
    for (int j = 0; j < 8; j++) {
        float nk = g_nk[hb*NSEQ + mb + j];
        rnk[j]  = 1.f/(nk + FEPS);
        rnkm[j] = 1.f/fmaxf(nk, FEPS);
        skv[j]  = g_sk[hb*NSEQ + mb + j];
    }
    __shared__ float red[4][6];
    double m[9]; for (int i = 0; i < 9; i++) m[i] = 0.0;
    for (int rr = 0; rr < 64; rr++) {
        int row = row0 + rr;
        const float* dr = g_dots + (size_t)row * NSEQ + mb;
        float nq = g_nq[row];
        float rq1 = 1.f/(nq + FEPS);
        float rq2 = 1.f/fmaxf(nq, FEPS);
        float c1 = g_muq[row];
        float c3 = c1*skm - g_qdkm[row];
        float4 d0 = *(const float4*)dr;
        float4 d1 = *(const float4*)(dr + 4);
        float dv[8] = {d0.x,d0.y,d0.z,d0.w,d1.x,d1.y,d1.z,d1.w};
        float pc=0.f, pc2=0.f, pv=0.f, pv2=0.f, pcv=0.f, pm=0.f;
#pragma unroll
        for (int j = 0; j < 8; j++) {
            float d = dv[j];
            float cosv = fminf(fmaxf(d*rq1*rnk[j], -0.95f), 0.95f);
            float cs   = fminf(fmaxf(d*rq2*rnkm[j], -0.95f), 0.95f);
            float marg = fminf(fmaxf(FGAMMA - cs, 0.f), 5.f);
            float cov  = fminf(fmaxf((d - c1*skv[j] + c3)*COVSCALE, -20.f), 20.f);
            pc += cosv; pc2 += cosv*cosv;
            pv += cov;  pv2 += cov*cov;
            pcv += cosv*cov; pm += marg;
        }
        float vals[6] = {pc, pc2, pv, pv2, pcv, pm};
#pragma unroll
        for (int i = 0; i < 6; i++)
            for (int o = 16; o > 0; o >>= 1)
                vals[i] += __shfl_down_sync(0xffffffffu, vals[i], o);
        int w = t >> 5, lane = t & 31;
        if (lane == 0) {
#pragma unroll
            for (int i = 0; i < 6; i++) red[w][i] = vals[i];
        }
        __syncthreads();
        if (t == 0) {
            float tot[6];
#pragma unroll
            for (int i = 0; i < 6; i++)
                tot[i] = red[0][i] + red[1][i] + red[2][i] + red[3][i];
            float var_row = tot[5] * (1.f/NSEQ);
            m[0] += tot[0]; m[1] += tot[1]; m[2] += tot[2];
            m[3] += tot[3]; m[4] += tot[4];
            m[5] += var_row;
            m[6] += (double)var_row * var_row;
            m[7] += (double)var_row * tot[0];
            m[8] += (double)var_row * tot[2];
        }
        __syncthreads();
    }
    if (t == 0) {
        for (int i = 0; i < 9; i++) atomicAdd(&g_mom[h][i], m[i]);
    }
}

/* ---------------- weight-predictor MLP + global stds + coeffs -------------- */
__global__ void predictor_kernel(const float* __restrict__ W1, const float* __restrict__ b1,
                                 const float* __restrict__ lng, const float* __restrict__ lnb,
                                 const float* __restrict__ W2, const float* __restrict__ b2,
                                 const float* __restrict__ W3, const float* __restrict__ b3,
                                 const float* __restrict__ wtemp) {
    __shared__ float z1[8][64];
    __shared__ float z2[8][64];
    __shared__ float z3[8][32];
    __shared__ float lg[8][3];
    __shared__ float wsh[8][3];
    __shared__ float stats[8][2];
    int tid = threadIdx.x;               /* 512 */
    {
        int h = tid >> 6, j = tid & 63;
        float s = b1[j];
        for (int i = 0; i < 64; i++) s += g_qg[h*64 + i] * W1[i*64 + j];
        for (int i = 0; i < 64; i++) s += g_kg[h*64 + i] * W1[(64+i)*64 + j];
        z1[h][j] = s;
    }
    __syncthreads();
    if (tid < 8) {
        float mu = 0.f;
        for (int i = 0; i < 64; i++) mu += z1[tid][i];
        mu *= (1.f/64.f);
        float var = 0.f;
        for (int i = 0; i < 64; i++) { float d = z1[tid][i] - mu; var += d*d; }
        var *= (1.f/64.f);
        stats[tid][0] = mu; stats[tid][1] = rsqrtf(var + 1e-5f);
    }
    __syncthreads();
    {
        int h = tid >> 6, j = tid & 63;
        float zz = (z1[h][j] - stats[h][0]) * stats[h][1] * lng[j] + lnb[j];
        z2[h][j] = fmaxf(zz, 0.f);
    }
    __syncthreads();
    if (tid < 256) {
        int h = tid >> 5, j = tid & 31;
        float s = b2[j];
        for (int i = 0; i < 64; i++) s += z2[h][i] * W2[i*32 + j];
        z3[h][j] = fmaxf(s, 0.f);
    }
    __syncthreads();
    if (tid < 24) {
        int h = tid / 3, c = tid % 3;
        float s = b3[c];
        for (int i = 0; i < 32; i++) s += z3[h][i] * W3[i*3 + c];
        lg[h][c] = s;
    }
    __syncthreads();
    if (tid < 8) {
        int h = tid;
        float mx = fmaxf(lg[h][0], fmaxf(lg[h][1], lg[h][2]));
        float e0 = expf(lg[h][0]-mx), e1 = expf(lg[h][1]-mx), e2 = expf(lg[h][2]-mx);
        float se = e0 + e1 + e2;
        float p0 = e0/se, p1 = e1/se, p2 = e2/se;
        float wt = fminf(fmaxf(wtemp[0], 0.1f), 10.f);
        float q0 = p0/wt, q1 = p1/wt, q2 = p2/wt;
        float mx2 = fmaxf(q0, fmaxf(q1, q2));
        float f0 = expf(q0-mx2), f1 = expf(q1-mx2), f2 = expf(q2-mx2);
        float sf = f0 + f1 + f2;
        wsh[h][0] = f0/sf*0.7f + 0.1f;
        wsh[h][1] = f1/sf*0.7f + 0.1f;
        wsh[h][2] = f2/sf*0.7f + 0.1f;
    }
    __syncthreads();
    if (tid == 0) {
        const double M = 67108864.0;
        double Sc=0, Sc2=0, Sv=0, Sv2=0, Svar=0, Svar2=0;
        for (int h = 0; h < 8; h++) {
            Sc += g_mom[h][0];  Sc2 += g_mom[h][1];
            Sv += g_mom[h][2];  Sv2 += g_mom[h][3];
            Svar += 1024.0*g_mom[h][5]; Svar2 += 1024.0*g_mom[h][6];
        }
        double cosn = sqrt(fmax((Sc2 - Sc*Sc/M)/(M-1.0), 0.0)) + 1e-6;
        double covn = sqrt(fmax((Sv2 - Sv*Sv/M)/(M-1.0), 0.0)) + 1e-6;
        double varn = sqrt(fmax((Svar2 - Svar*Svar/M)/(M-1.0), 0.0)) + 1e-6;
        double Sd = 0, Sd2 = 0;
        double ah[8], bh[8];
        for (int h = 0; h < 8; h++) {
            double a = (double)wsh[h][0] / cosn;
            double b = (double)wsh[h][1] * 0.3 / covn;
            double c = (double)wsh[h][2] * 0.3 / varn;
            ah[h] = a; bh[h] = b;
            Sd  += a*g_mom[h][0] + b*g_mom[h][2] + c*1024.0*g_mom[h][5];
            Sd2 += a*a*g_mom[h][1] + b*b*g_mom[h][3] + c*c*1024.0*g_mom[h][6]
                 + 2.0*a*b*g_mom[h][4] + 2.0*a*c*g_mom[h][7] + 2.0*b*c*g_mom[h][8];
        }
        double stdd = sqrt(fmax((Sd2 - Sd*Sd/M)/(M-1.0), 0.0));
        double temp = fmin(fmax(0.5 + stdd, 0.3), 3.0);
        for (int h = 0; h < 8; h++) {
            g_coef[h*2+0] = (float)(ah[h] / temp);
            g_coef[h*2+1] = (float)(bh[h] / temp);
        }
    }
}

/* ------------------ softmax over logits (var term cancels) ----------------- */
__global__ void softmax_kernel() {
    int row = blockIdx.x;                /* 65536 */
    int hb = row >> 10;
    int h = hb >> 3;
    int t = threadIdx.x;                 /* 128 */
    float A  = g_coef[h*2+0];
    float Bc = g_coef[h*2+1];
    float nq = g_nq[row];
    float rq1 = 1.f/(nq + FEPS);
    float c1 = g_muq[row];
    float c3 = c1*g_skm[hb] - g_qdkm[row];
    float* dr = g_dots + (size_t)row * NSEQ;
    int mb = t * 8;
    float4 d0 = *(const float4*)(dr + mb);
    float4 d1 = *(const float4*)(dr + mb + 4);
    float dv[8] = {d0.x,d0.y,d0.z,d0.w,d1.x,d1.y,d1.z,d1.w};
    float l[8];
    float mx = -1e30f;
#pragma unroll
    for (int j = 0; j < 8; j++) {
        float nk = g_nk[hb*NSEQ + mb + j];
        float cosv = fminf(fmaxf(dv[j]*rq1*(1.f/(nk + FEPS)), -0.95f), 0.95f);
        float cov  = fminf(fmaxf((dv[j] - c1*g_sk[hb*NSEQ + mb + j] + c3)*COVSCALE,
                                 -20.f), 20.f);
        float lv = A*cosv + Bc*cov;
        l[j] = lv;
        mx = fmaxf(mx, lv);
    }
    __shared__ float sred[4];
    __shared__ float sred2[4];
    int w = t >> 5, lane = t & 31;
    for (int o = 16; o > 0; o >>= 1) mx = fmaxf(mx, __shfl_xor_sync(0xffffffffu, mx, o));
    if (lane == 0) sred[w] = mx;
    __syncthreads();
    mx = fmaxf(fmaxf(sred[0], sred[1]), fmaxf(sred[2], sred[3]));
    float se = 0.f;
#pragma unroll
    for (int j = 0; j < 8; j++) { l[j] = __expf(l[j] - mx); se += l[j]; }
    for (int o = 16; o > 0; o >>= 1) se += __shfl_xor_sync(0xffffffffu, se, o);
    __syncthreads();
    if (lane == 0) sred2[w] = se;
    __syncthreads();
    float inv = 1.f/(sred2[0] + sred2[1] + sred2[2] + sred2[3]);
    *(float4*)(dr + mb)     = make_float4(l[0]*inv, l[1]*inv, l[2]*inv, l[3]*inv);
    *(float4*)(dr + mb + 4) = make_float4(l[4]*inv, l[5]*inv, l[6]*inv, l[7]*inv);
}

/* ----------------------- AV GEMM: P @ V -> g_oh[b,n,h*d] ------------------- */
__global__ void av_kernel() {
    int hb = blockIdx.y;
    int bm = blockIdx.x * 64;
    int h = hb >> 3, b_ = hb & 7;
    __shared__ __align__(16) float Ps[32][68];
    __shared__ __align__(16) float Vs[32][64];
    int tid = threadIdx.x, tx = tid & 15, ty = tid >> 4;
    const float* P = g_dots + ((size_t)hb << 20);
    const float* V = g_fv + (size_t)hb * NSEQ * DH;
    unsigned long long acc00 = 0ull, acc01 = 0ull, acc10 = 0ull, acc11 = 0ull;
    unsigned long long acc20 = 0ull, acc21 = 0ull, acc30 = 0ull, acc31 = 0ull;
    for (int k0 = 0; k0 < NSEQ; k0 += 32) {
#pragma unroll
        for (int j = 0; j < 2; j++) {
            int idx = tid + 256*j;
            int m = idx >> 3; int kq = (idx & 7) * 4;
            float4 vp = *(const float4*)(P + (size_t)(bm+m)*NSEQ + k0 + kq);
            Ps[kq+0][m] = vp.x; Ps[kq+1][m] = vp.y; Ps[kq+2][m] = vp.z; Ps[kq+3][m] = vp.w;
            int kk = idx >> 4; int nq4 = (idx & 15) * 4;
            float4 vv = *(const float4*)(V + (size_t)(k0+kk)*DH + nq4);
            *(float4*)&Vs[kk][nq4] = vv;
        }
        __syncthreads();
#pragma unroll
        for (int k = 0; k < 32; k++) {
            float4 a4 = *(const float4*)&Ps[k][ty*4];
            unsigned long long b0 = *(const unsigned long long*)&Vs[k][tx*4];
            unsigned long long b1 = *(const unsigned long long*)&Vs[k][tx*4+2];
            FMA2_STEP(a4, b0, b1);
        }
        __syncthreads();
    }
    float2 r0a = unpack2(acc00), r0b = unpack2(acc01);
    float2 r1a = unpack2(acc10), r1b = unpack2(acc11);
    float2 r2a = unpack2(acc20), r2b = unpack2(acc21);
    float2 r3a = unpack2(acc30), r3b = unpack2(acc31);
    float4 ov[4];
    ov[0] = make_float4(r0a.x, r0a.y, r0b.x, r0b.y);
    ov[1] = make_float4(r1a.x, r1a.y, r1b.x, r1b.y);
    ov[2] = make_float4(r2a.x, r2a.y, r2b.x, r2b.y);
    ov[3] = make_float4(r3a.x, r3a.y, r3b.x, r3b.y);
#pragma unroll
    for (int i = 0; i < 4; i++) {
        int n = bm + ty*4 + i;
        *(float4*)(g_oh + (size_t)(b_*NSEQ + n)*DIM + h*DH + tx*4) = ov[i];
    }
}

/* --------------------------------- launch ---------------------------------- */
extern "C" void kernel_launch(void* const* d_in, const int* in_sizes, int n_in,
                              void* d_out, int out_size) {
    (void)in_sizes; (void)n_in; (void)out_size;
    const float* q      = (const float*)d_in[0];
    const float* k      = (const float*)d_in[1];
    const float* v      = (const float*)d_in[2];
    const float* ln_g   = (const float*)d_in[3];
    const float* ln_b   = (const float*)d_in[4];
    const float* W_in   = (const float*)d_in[5];
    const float* wp_W1  = (const float*)d_in[6];
    const float* wp_b1  = (const float*)d_in[7];
    const float* wp_lng = (const float*)d_in[8];
    const float* wp_lnb = (const float*)d_in[9];
    const float* wp_W2  = (const float*)d_in[10];
    const float* wp_b2  = (const float*)d_in[11];
    const float* wp_W3  = (const float*)d_in[12];
    const float* wp_b3  = (const float*)d_in[13];
    const float* wtemp  = (const float*)d_in[14];
    const float* W_out  = (const float*)d_in[15];
    const float* b_out  = (const float*)d_in[16];
    float* out = (float*)d_out;

    zero_mom_kernel<<<1, 128>>>();

    dim3 gg(DIM/64, ROWS/64);
    ln_kernel<<<ROWS, 128>>>(q, ln_g, ln_b);
    gemm_proj_kernel<<<gg, 256>>>(W_in, 0);
    ln_kernel<<<ROWS, 128>>>(k, ln_g, ln_b);
    gemm_proj_kernel<<<gg, 256>>>(W_in, 1);
    ln_kernel<<<ROWS, 128>>>(v, ln_g, ln_b);
    gemm_proj_kernel<<<gg, 256>>>(W_in, 2);

    rowstats_kernel<<<16384, 256>>>();
    kmean_kernel<<<HB, 512>>>();
    qdkm_kernel<<<RT/8, 256>>>();
    qgkg_kernel<<<16, 512>>>();

    dots_kernel<<<dim3(16, 16, 64), 256>>>();
    moments_kernel<<<1024, 128>>>();
    predictor_kernel<<<1, 512>>>(wp_W1, wp_b1, wp_lng, wp_lnb,
                                 wp_W2, wp_b2, wp_W3, wp_b3, wtemp);
    softmax_kernel<<<RT, 128>>>();
    av_kernel<<<dim3(16, 64), 256>>>();
    gemm_out_kernel<<<gg, 256>>>(W_out, b_out, out);
}

// round 13
// speedup vs baseline: 1.1344x; 1.1344x over previous
#include <cuda_runtime.h>
#include <math.h>

#define HEADS 8
#define BATCH 8
#define NSEQ 1024
#define DIM 512
#define DH 64
#define HB 64            /* HEADS*BATCH */
#define ROWS 8192        /* BATCH*NSEQ  */
#define RT 65536         /* HB*NSEQ     */
#define FEPS 1e-6f
#define FGAMMA 0.01f
#define COVSCALE ((0.001f/1024.f)/(8.0f+1e-6f))

/* ------------------------- scratch (device globals) ------------------------ */
__device__ float g_xn[(size_t)ROWS*DIM];
__device__ float g_fq[(size_t)RT*DH];
__device__ float g_fk[(size_t)RT*DH];
__device__ float g_fv[(size_t)RT*DH];
__device__ float g_dots[(size_t)RT*NSEQ];
__device__ float g_nq[RT], g_muq[RT], g_nk[RT], g_sk[RT], g_qdkm[RT];
__device__ float g_kmean[HB*DH];
__device__ float g_skm[HB];
__device__ float g_qg[HEADS*DH], g_kg[HEADS*DH];
__device__ double g_mom[HEADS][9];
__device__ float g_coef[HEADS*2];
__device__ float g_oh[(size_t)ROWS*DIM];

/* 64 FMAs of the 8x8 microtile */
#define MICRO_8x8(a0, a1, b0, b1)                                              \
    do {                                                                       \
        float av0[4] = {(a0).x, (a0).y, (a0).z, (a0).w};                       \
        float av1[4] = {(a1).x, (a1).y, (a1).z, (a1).w};                       \
        float bv0[4] = {(b0).x, (b0).y, (b0).z, (b0).w};                       \
        float bv1[4] = {(b1).x, (b1).y, (b1).z, (b1).w};                       \
        _Pragma("unroll")                                                      \
        for (int i = 0; i < 4; ++i) {                                          \
            _Pragma("unroll")                                                  \
            for (int j = 0; j < 4; ++j) {                                      \
                acc[0][0][i][j] = fmaf(av0[i], bv0[j], acc[0][0][i][j]);       \
                acc[0][1][i][j] = fmaf(av0[i], bv1[j], acc[0][1][i][j]);       \
                acc[1][0][i][j] = fmaf(av1[i], bv0[j], acc[1][0][i][j]);       \
                acc[1][1][i][j] = fmaf(av1[i], bv1[j], acc[1][1][i][j]);       \
            }                                                                  \
        }                                                                      \
    } while (0)

/* ------------------------------ zero moments ------------------------------ */
__global__ void zero_mom_kernel() {
    int t = threadIdx.x;
    if (t < HEADS*9) ((double*)g_mom)[t] = 0.0;
}

/* ------------------------------- layernorm -------------------------------- */
__global__ void ln_kernel(const float* __restrict__ x,
                          const float* __restrict__ g,
                          const float* __restrict__ bb) {
    int row = blockIdx.x;
    int t = threadIdx.x;                 /* 128 threads */
    const float* xr = x + (size_t)row * DIM;
    float v[4]; float s = 0.f, s2 = 0.f;
#pragma unroll
    for (int i = 0; i < 4; i++) {
        float val = xr[t + 128*i];
        v[i] = val; s += val; s2 += val*val;
    }
    __shared__ float sh[8];
    for (int o = 16; o > 0; o >>= 1) {
        s  += __shfl_down_sync(0xffffffffu, s,  o);
        s2 += __shfl_down_sync(0xffffffffu, s2, o);
    }
    int w = t >> 5, lane = t & 31;
    if (lane == 0) { sh[w] = s; sh[4+w] = s2; }
    __syncthreads();
    if (t == 0) {
        float ts = 0.f, ts2 = 0.f;
        for (int i = 0; i < 4; i++) { ts += sh[i]; ts2 += sh[4+i]; }
        sh[0] = ts; sh[4] = ts2;
    }
    __syncthreads();
    float mu  = sh[0] * (1.f/DIM);
    float var = sh[4] * (1.f/DIM) - mu*mu;
    float inv = rsqrtf(var + 1e-5f);
    float* orow = g_xn + (size_t)row * DIM;
#pragma unroll
    for (int i = 0; i < 4; i++) {
        int c = t + 128*i;
        orow[c] = (v[i] - mu) * inv * g[c] + bb[c];
    }
}

/* ------------- proj GEMM: 128x128 tile, 8x8 micro, double-buffered --------- */
/* A = g_xn [8192 x 512] row-major; B = W [512 x 512] row-major (KxN).        */
__global__ void gemm_proj_kernel(const float* __restrict__ Bw, int which) {
    __shared__ float As[2][16][132];
    __shared__ float Bs[2][16][132];
    int tid = threadIdx.x;               /* 256 */
    int tx = tid & 15, ty = tid >> 4;
    int bm = blockIdx.y * 128, bn = blockIdx.x * 128;
    float acc[2][2][4][4] = {};
    int ar = tid >> 2, akq = (tid & 3) * 4;       /* A: rows ar, ar+64        */
    int bk = tid >> 5, bn4 = (tid & 31) * 4;      /* B: k rows bk, bk+8       */
    const float* Ag = g_xn + (size_t)bm * DIM;
    const float* Bg = Bw + bn;

    {   /* stage chunk 0 */
        float4 a0 = *(const float4*)(Ag + (size_t)ar * DIM + akq);
        float4 a1 = *(const float4*)(Ag + (size_t)(ar+64) * DIM + akq);
        As[0][akq+0][ar] = a0.x; As[0][akq+1][ar] = a0.y;
        As[0][akq+2][ar] = a0.z; As[0][akq+3][ar] = a0.w;
        As[0][akq+0][ar+64] = a1.x; As[0][akq+1][ar+64] = a1.y;
        As[0][akq+2][ar+64] = a1.z; As[0][akq+3][ar+64] = a1.w;
        *(float4*)&Bs[0][bk][bn4]   = *(const float4*)(Bg + (size_t)bk * DIM + bn4);
        *(float4*)&Bs[0][bk+8][bn4] = *(const float4*)(Bg + (size_t)(bk+8) * DIM + bn4);
    }
    __syncthreads();
    for (int c = 0; c < 32; ++c) {
        int buf = c & 1;
        float4 pa0, pa1, pb0, pb1;
        if (c + 1 < 32) {
            const float* An = Ag + (c+1) * 16;
            const float* Bn = Bg + (size_t)((c+1) * 16) * DIM;
            pa0 = *(const float4*)(An + (size_t)ar * DIM + akq);
            pa1 = *(const float4*)(An + (size_t)(ar+64) * DIM + akq);
            pb0 = *(const float4*)(Bn + (size_t)bk * DIM + bn4);
            pb1 = *(const float4*)(Bn + (size_t)(bk+8) * DIM + bn4);
        }
#pragma unroll
        for (int k = 0; k < 16; ++k) {
            float4 a0 = *(const float4*)&As[buf][k][ty*4];
            float4 a1 = *(const float4*)&As[buf][k][64 + ty*4];
            float4 b0 = *(const float4*)&Bs[buf][k][tx*4];
            float4 b1 = *(const float4*)&Bs[buf][k][64 + tx*4];
            MICRO_8x8(a0, a1, b0, b1);
        }
        if (c + 1 < 32) {
            int nb = buf ^ 1;
            As[nb][akq+0][ar] = pa0.x; As[nb][akq+1][ar] = pa0.y;
            As[nb][akq+2][ar] = pa0.z; As[nb][akq+3][ar] = pa0.w;
            As[nb][akq+0][ar+64] = pa1.x; As[nb][akq+1][ar+64] = pa1.y;
            As[nb][akq+2][ar+64] = pa1.z; As[nb][akq+3][ar+64] = pa1.w;
            *(float4*)&Bs[nb][bk][bn4]   = pb0;
            *(float4*)&Bs[nb][bk+8][bn4] = pb1;
        }
        __syncthreads();
    }
    float* C = (which == 0) ? g_fq : ((which == 1) ? g_fk : g_fv);
#pragma unroll
    for (int jj = 0; jj < 2; ++jj) {
        int col0 = bn + jj*64 + tx*4;
        int h_ = col0 >> 6, d = col0 & 63;
#pragma unroll
        for (int ii = 0; ii < 2; ++ii) {
#pragma unroll
            for (int i = 0; i < 4; ++i) {
                int r = bm + ii*64 + ty*4 + i;
                int b_ = r >> 10, n = r & 1023;
                *(float4*)(C + (((size_t)(h_*BATCH + b_)) << 16) + (n << 6) + d) =
                    make_float4(acc[ii][jj][i][0], acc[ii][jj][i][1],
                                acc[ii][jj][i][2], acc[ii][jj][i][3]);
            }
        }
    }
}

/* ------------- out GEMM: same core, plain writeback + bias ----------------- */
__global__ void gemm_out_kernel(const float* __restrict__ Bw,
                                const float* __restrict__ bias,
                                float* __restrict__ Cout) {
    __shared__ float As[2][16][132];
    __shared__ float Bs[2][16][132];
    int tid = threadIdx.x;
    int tx = tid & 15, ty = tid >> 4;
    int bm = blockIdx.y * 128, bn = blockIdx.x * 128;
    float acc[2][2][4][4] = {};
    int ar = tid >> 2, akq = (tid & 3) * 4;
    int bk = tid >> 5, bn4 = (tid & 31) * 4;
    const float* Ag = g_oh + (size_t)bm * DIM;
    const float* Bg = Bw + bn;
    {
        float4 a0 = *(const float4*)(Ag + (size_t)ar * DIM + akq);
        float4 a1 = *(const float4*)(Ag + (size_t)(ar+64) * DIM + akq);
        As[0][akq+0][ar] = a0.x; As[0][akq+1][ar] = a0.y;
        As[0][akq+2][ar] = a0.z; As[0][akq+3][ar] = a0.w;
        As[0][akq+0][ar+64] = a1.x; As[0][akq+1][ar+64] = a1.y;
        As[0][akq+2][ar+64] = a1.z; As[0][akq+3][ar+64] = a1.w;
        *(float4*)&Bs[0][bk][bn4]   = *(const float4*)(Bg + (size_t)bk * DIM + bn4);
        *(float4*)&Bs[0][bk+8][bn4] = *(const float4*)(Bg + (size_t)(bk+8) * DIM + bn4);
    }
    __syncthreads();
    for (int c = 0; c < 32; ++c) {
        int buf = c & 1;
        float4 pa0, pa1, pb0, pb1;
        if (c + 1 < 32) {
            const float* An = Ag + (c+1) * 16;
            const float* Bn = Bg + (size_t)((c+1) * 16) * DIM;
            pa0 = *(const float4*)(An + (size_t)ar * DIM + akq);
            pa1 = *(const float4*)(An + (size_t)(ar+64) * DIM + akq);
            pb0 = *(const float4*)(Bn + (size_t)bk * DIM + bn4);
            pb1 = *(const float4*)(Bn + (size_t)(bk+8) * DIM + bn4);
        }
#pragma unroll
        for (int k = 0; k < 16; ++k) {
            float4 a0 = *(const float4*)&As[buf][k][ty*4];
            float4 a1 = *(const float4*)&As[buf][k][64 + ty*4];
            float4 b0 = *(const float4*)&Bs[buf][k][tx*4];
            float4 b1 = *(const float4*)&Bs[buf][k][64 + tx*4];
            MICRO_8x8(a0, a1, b0, b1);
        }
        if (c + 1 < 32) {
            int nb = buf ^ 1;
            As[nb][akq+0][ar] = pa0.x; As[nb][akq+1][ar] = pa0.y;
            As[nb][akq+2][ar] = pa0.z; As[nb][akq+3][ar] = pa0.w;
            As[nb][akq+0][ar+64] = pa1.x; As[nb][akq+1][ar+64] = pa1.y;
            As[nb][akq+2][ar+64] = pa1.z; As[nb][akq+3][ar+64] = pa1.w;
            *(float4*)&Bs[nb][bk][bn4]   = pb0;
            *(float4*)&Bs[nb][bk+8][bn4] = pb1;
        }
        __syncthreads();
    }
#pragma unroll
    for (int jj = 0; jj < 2; ++jj) {
        int col0 = bn + jj*64 + tx*4;
        float4 bv = *(const float4*)(bias + col0);
#pragma unroll
        for (int ii = 0; ii < 2; ++ii) {
#pragma unroll
            for (int i = 0; i < 4; ++i) {
                int r = bm + ii*64 + ty*4 + i;
                *(float4*)(Cout + (size_t)r*DIM + col0) =
                    make_float4(acc[ii][jj][i][0] + bv.x, acc[ii][jj][i][1] + bv.y,
                                acc[ii][jj][i][2] + bv.z, acc[ii][jj][i][3] + bv.w);
            }
        }
    }
}

/* ---------------- dots GEMM: Q @ K^T, both operands [N x K] ---------------- */
__global__ void dots_kernel() {
    __shared__ float As[2][16][132];
    __shared__ float Bs[2][16][132];
    int hb = blockIdx.z;
    int bm = blockIdx.y * 128, bn = blockIdx.x * 128;
    int tid = threadIdx.x;
    int tx = tid & 15, ty = tid >> 4;
    float acc[2][2][4][4] = {};
    int ar = tid >> 2, akq = (tid & 3) * 4;
    const float* Ag = g_fq + ((size_t)hb << 16) + (size_t)bm * DH;
    const float* Bg = g_fk + ((size_t)hb << 16) + (size_t)bn * DH;
    {
        float4 a0 = *(const float4*)(Ag + (size_t)ar * DH + akq);
        float4 a1 = *(const float4*)(Ag + (size_t)(ar+64) * DH + akq);
        As[0][akq+0][ar] = a0.x; As[0][akq+1][ar] = a0.y;
        As[0][akq+2][ar] = a0.z; As[0][akq+3][ar] = a0.w;
        As[0][akq+0][ar+64] = a1.x; As[0][akq+1][ar+64] = a1.y;
        As[0][akq+2][ar+64] = a1.z; As[0][akq+3][ar+64] = a1.w;
        float4 b0 = *(const float4*)(Bg + (size_t)ar * DH + akq);
        float4 b1 = *(const float4*)(Bg + (size_t)(ar+64) * DH + akq);
        Bs[0][akq+0][ar] = b0.x; Bs[0][akq+1][ar] = b0.y;
        Bs[0][akq+2][ar] = b0.z; Bs[0][akq+3][ar] = b0.w;
        Bs[0][akq+0][ar+64] = b1.x; Bs[0][akq+1][ar+64] = b1.y;
        Bs[0][akq+2][ar+64] = b1.z; Bs[0][akq+3][ar+64] = b1.w;
    }
    __syncthreads();
    for (int c = 0; c < 4; ++c) {
        int buf = c & 1;
        float4 pa0, pa1, pb0, pb1;
        if (c + 1 < 4) {
            const float* An = Ag + (c+1) * 16;
            const float* Bn = Bg + (c+1) * 16;
            pa0 = *(const float4*)(An + (size_t)ar * DH + akq);
            pa1 = *(const float4*)(An + (size_t)(ar+64) * DH + akq);
            pb0 = *(const float4*)(Bn + (size_t)ar * DH + akq);
            pb1 = *(const float4*)(Bn + (size_t)(ar+64) * DH + akq);
        }
#pragma unroll
        for (int k = 0; k < 16; ++k) {
            float4 a0 = *(const float4*)&As[buf][k][ty*4];
            float4 a1 = *(const float4*)&As[buf][k][64 + ty*4];
            float4 b0 = *(const float4*)&Bs[buf][k][tx*4];
            float4 b1 = *(const float4*)&Bs[buf][k][64 + tx*4];
            MICRO_8x8(a0, a1, b0, b1);
        }
        if (c + 1 < 4) {
            int nb = buf ^ 1;
            As[nb][akq+0][ar] = pa0.x; As[nb][akq+1][ar] = pa0.y;
            As[nb][akq+2][ar] = pa0.z; As[nb][akq+3][ar] = pa0.w;
            As[nb][akq+0][ar+64] = pa1.x; As[nb][akq+1][ar+64] = pa1.y;
            As[nb][akq+2][ar+64] = pa1.z; As[nb][akq+3][ar+64] = pa1.w;
            Bs[nb][akq+0][ar] = pb0.x; Bs[nb][akq+1][ar] = pb0.y;
            Bs[nb][akq+2][ar] = pb0.z; Bs[nb][akq+3][ar] = pb0.w;
            Bs[nb][akq+0][ar+64] = pb1.x; Bs[nb][akq+1][ar+64] = pb1.y;
            Bs[nb][akq+2][ar+64] = pb1.z; Bs[nb][akq+3][ar+64] = pb1.w;
        }
        __syncthreads();
    }
    float* D = g_dots + ((size_t)hb << 20);
#pragma unroll
    for (int ii = 0; ii < 2; ++ii) {
#pragma unroll
        for (int i = 0; i < 4; ++i) {
            int gr = bm + ii*64 + ty*4 + i;
#pragma unroll
            for (int jj = 0; jj < 2; ++jj) {
                int gc = bn + jj*64 + tx*4;
                *(float4*)(D + (size_t)gr * NSEQ + gc) =
                    make_float4(acc[ii][jj][i][0], acc[ii][jj][i][1],
                                acc[ii][jj][i][2], acc[ii][jj][i][3]);
            }
        }
    }
}

/* ----------------- AV GEMM: 128x64 tile, 8x4 micro, P @ V ------------------ */
__global__ void av_kernel() {
    __shared__ float As[2][16][132];
    __shared__ float Bs[2][16][68];
    int hb = blockIdx.y;
    int bm = blockIdx.x * 128;
    int h = hb >> 3, b_ = hb & 7;
    int tid = threadIdx.x;
    int tx = tid & 15, ty = tid >> 4;
    float acc[2][1][4][4] = {};
    int ar = tid >> 2, akq = (tid & 3) * 4;
    int bk = tid >> 4, bn4 = (tid & 15) * 4;     /* 16 k-rows x 64 cols, 1/thr */
    const float* Ag = g_dots + ((size_t)hb << 20) + (size_t)bm * NSEQ;
    const float* Bg = g_fv + ((size_t)hb << 16);
    {
        float4 a0 = *(const float4*)(Ag + (size_t)ar * NSEQ + akq);
        float4 a1 = *(const float4*)(Ag + (size_t)(ar+64) * NSEQ + akq);
        As[0][akq+0][ar] = a0.x; As[0][akq+1][ar] = a0.y;
        As[0][akq+2][ar] = a0.z; As[0][akq+3][ar] = a0.w;
        As[0][akq+0][ar+64] = a1.x; As[0][akq+1][ar+64] = a1.y;
        As[0][akq+2][ar+64] = a1.z; As[0][akq+3][ar+64] = a1.w;
        *(float4*)&Bs[0][bk][bn4] = *(const float4*)(Bg + (size_t)bk * DH + bn4);
    }
    __syncthreads();
    for (int c = 0; c < 64; ++c) {
        int buf = c & 1;
        float4 pa0, pa1, pb0;
        if (c + 1 < 64) {
            const float* An = Ag + (c+1) * 16;
            const float* Bn = Bg + (size_t)((c+1) * 16) * DH;
            pa0 = *(const float4*)(An + (size_t)ar * NSEQ + akq);
            pa1 = *(const float4*)(An + (size_t)(ar+64) * NSEQ + akq);
            pb0 = *(const float4*)(Bn + (size_t)bk * DH + bn4);
        }
#pragma unroll
        for (int k = 0; k < 16; ++k) {
            float4 a0 = *(const float4*)&As[buf][k][ty*4];
            float4 a1 = *(const float4*)&As[buf][k][64 + ty*4];
            float4 b0 = *(const float4*)&Bs[buf][k][tx*4];
            float av0[4] = {a0.x, a0.y, a0.z, a0.w};
            float av1[4] = {a1.x, a1.y, a1.z, a1.w};
            float bv0[4] = {b0.x, b0.y, b0.z, b0.w};
#pragma unroll
            for (int i = 0; i < 4; ++i)
#pragma unroll
                for (int j = 0; j < 4; ++j) {
                    acc[0][0][i][j] = fmaf(av0[i], bv0[j], acc[0][0][i][j]);
                    acc[1][0][i][j] = fmaf(av1[i], bv0[j], acc[1][0][i][j]);
                }
        }
        if (c + 1 < 64) {
            int nb = buf ^ 1;
            As[nb][akq+0][ar] = pa0.x; As[nb][akq+1][ar] = pa0.y;
            As[nb][akq+2][ar] = pa0.z; As[nb][akq+3][ar] = pa0.w;
            As[nb][akq+0][ar+64] = pa1.x; As[nb][akq+1][ar+64] = pa1.y;
            As[nb][akq+2][ar+64] = pa1.z; As[nb][akq+3][ar+64] = pa1.w;
            *(float4*)&Bs[nb][bk][bn4] = pb0;
        }
        __syncthreads();
    }
#pragma unroll
    for (int ii = 0; ii < 2; ++ii) {
#pragma unroll
        for (int i = 0; i < 4; ++i) {
            int n = bm + ii*64 + ty*4 + i;
            *(float4*)(g_oh + (size_t)(b_*NSEQ + n)*DIM + h*DH + tx*4) =
                make_float4(acc[ii][0][i][0], acc[ii][0][i][1],
                            acc[ii][0][i][2], acc[ii][0][i][3]);
        }
    }
}

/* ----------------- per-row stats: norms / means / sums --------------------- */
__global__ void rowstats_kernel() {
    int blk = blockIdx.x;                /* 16384 */
    int tensor = blk >> 13;
    int rowbase = (blk & 8191) * 8;
    int w = threadIdx.x >> 5, lane = threadIdx.x & 31;
    int row = rowbase + w;
    const float* f = (tensor == 0) ? g_fq : g_fk;
    float a = f[(size_t)row*DH + lane];
    float b = f[(size_t)row*DH + 32 + lane];
    float s = a + b, s2 = a*a + b*b;
    for (int o = 16; o > 0; o >>= 1) {
        s  += __shfl_down_sync(0xffffffffu, s,  o);
        s2 += __shfl_down_sync(0xffffffffu, s2, o);
    }
    if (lane == 0) {
        if (tensor == 0) { g_nq[row] = sqrtf(s2); g_muq[row] = s * (1.f/DH); }
        else             { g_nk[row] = sqrtf(s2); g_sk[row] = s; }
    }
}

/* ------------------------- kmean over n, skm over d ------------------------ */
__global__ void kmean_kernel() {
    int hb = blockIdx.x;
    int grp = threadIdx.x >> 6;
    int dd = threadIdx.x & 63;
    float acc = 0.f;
    const float* base = g_fk + (size_t)hb * NSEQ * DH;
    for (int n = grp; n < NSEQ; n += 8) acc += base[(size_t)n*DH + dd];
    __shared__ float sh[8][64];
    sh[grp][dd] = acc;
    __syncthreads();
    if (grp == 0) {
        float t = 0.f;
#pragma unroll
        for (int g = 0; g < 8; g++) t += sh[g][dd];
        t *= (1.f/NSEQ);
        g_kmean[hb*DH + dd] = t;
        sh[0][dd] = t;
    }
    __syncthreads();
    if (threadIdx.x == 0) {
        float t = 0.f;
        for (int i = 0; i < DH; i++) t += sh[0][i];
        g_skm[hb] = t;
    }
}

/* --------------------------- q . kmean per row ----------------------------- */
__global__ void qdkm_kernel() {
    int row = blockIdx.x*8 + (threadIdx.x >> 5);
    int lane = threadIdx.x & 31;
    int hb = row >> 10;
    float a = g_fq[(size_t)row*DH + lane]      * g_kmean[hb*DH + lane]
            + g_fq[(size_t)row*DH + 32 + lane] * g_kmean[hb*DH + 32 + lane];
    for (int o = 16; o > 0; o >>= 1) a += __shfl_down_sync(0xffffffffu, a, o);
    if (lane == 0) g_qdkm[row] = a;
}

/* --------------------- q_g / k_g: mean over (b,n) per head ----------------- */
__global__ void qgkg_kernel() {
    int t = blockIdx.x >> 3;
    int h = blockIdx.x & 7;
    const float* f = (t == 0) ? g_fq : g_fk;
    int grp = threadIdx.x >> 6, dd = threadIdx.x & 63;
    float acc = 0.f;
    const float* base = f + (size_t)h * BATCH * NSEQ * DH;
    for (int idx = grp; idx < BATCH*NSEQ; idx += 8) acc += base[(size_t)idx*DH + dd];
    __shared__ float sh[8][64];
    sh[grp][dd] = acc;
    __syncthreads();
    if (grp == 0) {
        float tt = 0.f;
#pragma unroll
        for (int g = 0; g < 8; g++) tt += sh[g][dd];
        float* outp = (t == 0) ? g_qg : g_kg;
        outp[h*DH + dd] = tt * (1.f/(BATCH*NSEQ));
    }
}

/* ----------------------- global moment accumulation ------------------------ */
__global__ void moments_kernel() {
    int blk = blockIdx.x;                /* 1024 blocks, 64 rows each */
    int row0 = blk * 64;
    int h = row0 >> 13;
    int hb = row0 >> 10;
    int t = threadIdx.x;                 /* 128 */
    int mb = t * 8;
    float rnk[8], rnkm[8], skv[8];
    const float skm = g_skm[hb];
#pragma unroll
    for (int j = 0; j < 8; j++) {
        float nk = g_nk[hb*NSEQ + mb + j];
        rnk[j]  = 1.f/(nk + FEPS);
        rnkm[j] = 1.f/fmaxf(nk, FEPS);
        skv[j]  = g_sk[hb*NSEQ + mb + j];
    }
    __shared__ float red[4][6];
    double m[9]; for (int i = 0; i < 9; i++) m[i] = 0.0;
    for (int rr = 0; rr < 64; rr++) {
        int row = row0 + rr;
        const float* dr = g_dots + (size_t)row * NSEQ + mb;
        float nq = g_nq[row];
        float rq1 = 1.f/(nq + FEPS);
        float rq2 = 1.f/fmaxf(nq, FEPS);
        float c1 = g_muq[row];
        float c3 = c1*skm - g_qdkm[row];
        float4 d0 = *(const float4*)dr;
        float4 d1 = *(const float4*)(dr + 4);
        float dv[8] = {d0.x,d0.y,d0.z,d0.w,d1.x,d1.y,d1.z,d1.w};
        float pc=0.f, pc2=0.f, pv=0.f, pv2=0.f, pcv=0.f, pm=0.f;
#pragma unroll
        for (int j = 0; j < 8; j++) {
            float d = dv[j];
            float cosv = fminf(fmaxf(d*rq1*rnk[j], -0.95f), 0.95f);
            float cs   = fminf(fmaxf(d*rq2*rnkm[j], -0.95f), 0.95f);
            float marg = fminf(fmaxf(FGAMMA - cs, 0.f), 5.f);
            float cov  = fminf(fmaxf((d - c1*skv[j] + c3)*COVSCALE, -20.f), 20.f);
            pc += cosv; pc2 += cosv*cosv;
            pv += cov;  pv2 += cov*cov;
            pcv += cosv*cov; pm += marg;
        }
        float vals[6] = {pc, pc2, pv, pv2, pcv, pm};
#pragma unroll
        for (int i = 0; i < 6; i++)
            for (int o = 16; o > 0; o >>= 1)
                vals[i] += __shfl_down_sync(0xffffffffu, vals[i], o);
        int w = t >> 5, lane = t & 31;
        if (lane == 0) {
#pragma unroll
            for (int i = 0; i < 6; i++) red[w][i] = vals[i];
        }
        __syncthreads();
        if (t == 0) {
            float tot[6];
#pragma unroll
            for (int i = 0; i < 6; i++)
                tot[i] = red[0][i] + red[1][i] + red[2][i] + red[3][i];
            float var_row = tot[5] * (1.f/NSEQ);
            m[0] += tot[0]; m[1] += tot[1]; m[2] += tot[2];
            m[3] += tot[3]; m[4] += tot[4];
            m[5] += var_row;
            m[6] += (double)var_row * var_row;
            m[7] += (double)var_row * tot[0];
            m[8] += (double)var_row * tot[2];
        }
        __syncthreads();
    }
    if (t == 0) {
        for (int i = 0; i < 9; i++) atomicAdd(&g_mom[h][i], m[i]);
    }
}

/* ---------------- weight-predictor MLP + global stds + coeffs -------------- */
__global__ void predictor_kernel(const float* __restrict__ W1, const float* __restrict__ b1,
                                 const float* __restrict__ lng, const float* __restrict__ lnb,
                                 const float* __restrict__ W2, const float* __restrict__ b2,
                                 const float* __restrict__ W3, const float* __restrict__ b3,
                                 const float* __restrict__ wtemp) {
    __shared__ float z1[8][64];
    __shared__ float z2[8][64];
    __shared__ float z3[8][32];
    __shared__ float lg[8][3];
    __shared__ float wsh[8][3];
    __shared__ float stats[8][2];
    int tid = threadIdx.x;               /* 512 */
    {
        int h = tid >> 6, j = tid & 63;
        float s = b1[j];
        for (int i = 0; i < 64; i++) s += g_qg[h*64 + i] * W1[i*64 + j];
        for (int i = 0; i < 64; i++) s += g_kg[h*64 + i] * W1[(64+i)*64 + j];
        z1[h][j] = s;
    }
    __syncthreads();
    if (tid < 8) {
        float mu = 0.f;
        for (int i = 0; i < 64; i++) mu += z1[tid][i];
        mu *= (1.f/64.f);
        float var = 0.f;
        for (int i = 0; i < 64; i++) { float d = z1[tid][i] - mu; var += d*d; }
        var *= (1.f/64.f);
        stats[tid][0] = mu; stats[tid][1] = rsqrtf(var + 1e-5f);
    }
    __syncthreads();
    {
        int h = tid >> 6, j = tid & 63;
        float zz = (z1[h][j] - stats[h][0]) * stats[h][1] * lng[j] + lnb[j];
        z2[h][j] = fmaxf(zz, 0.f);
    }
    __syncthreads();
    if (tid < 256) {
        int h = tid >> 5, j = tid & 31;
        float s = b2[j];
        for (int i = 0; i < 64; i++) s += z2[h][i] * W2[i*32 + j];
        z3[h][j] = fmaxf(s, 0.f);
    }
    __syncthreads();
    if (tid < 24) {
        int h = tid / 3, c = tid % 3;
        float s = b3[c];
        for (int i = 0; i < 32; i++) s += z3[h][i] * W3[i*3 + c];
        lg[h][c] = s;
    }
    __syncthreads();
    if (tid < 8) {
        int h = tid;
        float mx = fmaxf(lg[h][0], fmaxf(lg[h][1], lg[h][2]));
        float e0 = expf(lg[h][0]-mx), e1 = expf(lg[h][1]-mx), e2 = expf(lg[h][2]-mx);
        float se = e0 + e1 + e2;
        float p0 = e0/se, p1 = e1/se, p2 = e2/se;
        float wt = fminf(fmaxf(wtemp[0], 0.1f), 10.f);
        float q0 = p0/wt, q1 = p1/wt, q2 = p2/wt;
        float mx2 = fmaxf(q0, fmaxf(q1, q2));
        float f0 = expf(q0-mx2), f1 = expf(q1-mx2), f2 = expf(q2-mx2);
        float sf = f0 + f1 + f2;
        wsh[h][0] = f0/sf*0.7f + 0.1f;
        wsh[h][1] = f1/sf*0.7f + 0.1f;
        wsh[h][2] = f2/sf*0.7f + 0.1f;
    }
    __syncthreads();
    if (tid == 0) {
        const double M = 67108864.0;
        double Sc=0, Sc2=0, Sv=0, Sv2=0, Svar=0, Svar2=0;
        for (int h = 0; h < 8; h++) {
            Sc += g_mom[h][0];  Sc2 += g_mom[h][1];
            Sv += g_mom[h][2];  Sv2 += g_mom[h][3];
            Svar += 1024.0*g_mom[h][5]; Svar2 += 1024.0*g_mom[h][6];
        }
        double cosn = sqrt(fmax((Sc2 - Sc*Sc/M)/(M-1.0), 0.0)) + 1e-6;
        double covn = sqrt(fmax((Sv2 - Sv*Sv/M)/(M-1.0), 0.0)) + 1e-6;
        double varn = sqrt(fmax((Svar2 - Svar*Svar/M)/(M-1.0), 0.0)) + 1e-6;
        double Sd = 0, Sd2 = 0;
        double ah[8], bh[8];
        for (int h = 0; h < 8; h++) {
            double a = (double)wsh[h][0] / cosn;
            double b = (double)wsh[h][1] * 0.3 / covn;
            double c = (double)wsh[h][2] * 0.3 / varn;
            ah[h] = a; bh[h] = b;
            Sd  += a*g_mom[h][0] + b*g_mom[h][2] + c*1024.0*g_mom[h][5];
            Sd2 += a*a*g_mom[h][1] + b*b*g_mom[h][3] + c*c*1024.0*g_mom[h][6]
                 + 2.0*a*b*g_mom[h][4] + 2.0*a*c*g_mom[h][7] + 2.0*b*c*g_mom[h][8];
        }
        double stdd = sqrt(fmax((Sd2 - Sd*Sd/M)/(M-1.0), 0.0));
        double temp = fmin(fmax(0.5 + stdd, 0.3), 3.0);
        for (int h = 0; h < 8; h++) {
            g_coef[h*2+0] = (float)(ah[h] / temp);
            g_coef[h*2+1] = (float)(bh[h] / temp);
        }
    }
}

/* ------------------ softmax over logits (var term cancels) ----------------- */
__global__ void softmax_kernel() {
    int row = blockIdx.x;                /* 65536 */
    int hb = row >> 10;
    int h = hb >> 3;
    int t = threadIdx.x;                 /* 128 */
    float A  = g_coef[h*2+0];
    float Bc = g_coef[h*2+1];
    float nq = g_nq[row];
    float rq1 = 1.f/(nq + FEPS);
    float c1 = g_muq[row];
    float c3 = c1*g_skm[hb] - g_qdkm[row];
    float* dr = g_dots + (size_t)row * NSEQ;
    int mb = t * 8;
    float4 d0 = *(const float4*)(dr + mb);
    float4 d1 = *(const float4*)(dr + mb + 4);
    float dv[8] = {d0.x,d0.y,d0.z,d0.w,d1.x,d1.y,d1.z,d1.w};
    float l[8];
    float mx = -1e30f;
#pragma unroll
    for (int j = 0; j < 8; j++) {
        float nk = g_nk[hb*NSEQ + mb + j];
        float cosv = fminf(fmaxf(dv[j]*rq1*(1.f/(nk + FEPS)), -0.95f), 0.95f);
        float cov  = fminf(fmaxf((dv[j] - c1*g_sk[hb*NSEQ + mb + j] + c3)*COVSCALE,
                                 -20.f), 20.f);
        float lv = A*cosv + Bc*cov;
        l[j] = lv;
        mx = fmaxf(mx, lv);
    }
    __shared__ float sred[4];
    __shared__ float sred2[4];
    int w = t >> 5, lane = t & 31;
    for (int o = 16; o > 0; o >>= 1) mx = fmaxf(mx, __shfl_xor_sync(0xffffffffu, mx, o));
    if (lane == 0) sred[w] = mx;
    __syncthreads();
    mx = fmaxf(fmaxf(sred[0], sred[1]), fmaxf(sred[2], sred[3]));
    float se = 0.f;
#pragma unroll
    for (int j = 0; j < 8; j++) { l[j] = __expf(l[j] - mx); se += l[j]; }
    for (int o = 16; o > 0; o >>= 1) se += __shfl_xor_sync(0xffffffffu, se, o);
    __syncthreads();
    if (lane == 0) sred2[w] = se;
    __syncthreads();
    float inv = 1.f/(sred2[0] + sred2[1] + sred2[2] + sred2[3]);
    *(float4*)(dr + mb)     = make_float4(l[0]*inv, l[1]*inv, l[2]*inv, l[3]*inv);
    *(float4*)(dr + mb + 4) = make_float4(l[4]*inv, l[5]*inv, l[6]*inv, l[7]*inv);
}

/* --------------------------------- launch ---------------------------------- */
extern "C" void kernel_launch(void* const* d_in, const int* in_sizes, int n_in,
                              void* d_out, int out_size) {
    (void)in_sizes; (void)n_in; (void)out_size;
    const float* q      = (const float*)d_in[0];
    const float* k      = (const float*)d_in[1];
    const float* v      = (const float*)d_in[2];
    const float* ln_g   = (const float*)d_in[3];
    const float* ln_b   = (const float*)d_in[4];
    const float* W_in   = (const float*)d_in[5];
    const float* wp_W1  = (const float*)d_in[6];
    const float* wp_b1  = (const float*)d_in[7];
    const float* wp_lng = (const float*)d_in[8];
    const float* wp_lnb = (const float*)d_in[9];
    const float* wp_W2  = (const float*)d_in[10];
    const float* wp_b2  = (const float*)d_in[11];
    const float* wp_W3  = (const float*)d_in[12];
    const float* wp_b3  = (const float*)d_in[13];
    const float* wtemp  = (const float*)d_in[14];
    const float* W_out  = (const float*)d_in[15];
    const float* b_out  = (const float*)d_in[16];
    float* out = (float*)d_out;

    zero_mom_kernel<<<1, 128>>>();

    dim3 gg(DIM/128, ROWS/128);
    ln_kernel<<<ROWS, 128>>>(q, ln_g, ln_b);
    gemm_proj_kernel<<<gg, 256>>>(W_in, 0);
    ln_kernel<<<ROWS, 128>>>(k, ln_g, ln_b);
    gemm_proj_kernel<<<gg, 256>>>(W_in, 1);
    ln_kernel<<<ROWS, 128>>>(v, ln_g, ln_b);
    gemm_proj_kernel<<<gg, 256>>>(W_in, 2);

    rowstats_kernel<<<16384, 256>>>();
    kmean_kernel<<<HB, 512>>>();
    qdkm_kernel<<<RT/8, 256>>>();
    qgkg_kernel<<<16, 512>>>();

    dots_kernel<<<dim3(8, 8, 64), 256>>>();
    moments_kernel<<<1024, 128>>>();
    predictor_kernel<<<1, 512>>>(wp_W1, wp_b1, wp_lng, wp_lnb,
                                 wp_W2, wp_b2, wp_W3, wp_b3, wtemp);
    softmax_kernel<<<RT, 128>>>();
    av_kernel<<<dim3(8, 64), 256>>>();
    gemm_out_kernel<<<gg, 256>>>(W_out, b_out, out);
}